// round 3
// baseline (speedup 1.0000x reference)
#include <cuda_runtime.h>
#include <cstdint>

// Problem constants
#define EV    50000
#define EDIM  128
#define HDIM  64
#define GDIM  256          // 4*H
#define BSZ   512
#define SLEN  512
#define NB    4            // batch elements per recurrence CTA

// -------- scratch: xproj0 [B][S][4H] fp32 = 268 MB (device global, no alloc) -----
__device__ float g_xproj[(size_t)BSZ * SLEN * GDIM];

// ---------------- helpers ----------------
__device__ __forceinline__ uint32_t smem_u32(const void* p) {
    uint32_t a;
    asm("{ .reg .u64 t; cvta.to.shared.u64 t, %1; cvt.u32.u64 %0, t; }"
        : "=r"(a) : "l"(p));
    return a;
}

// packed fp32x2 FMA (Blackwell): d = a*b + c on two lanes
__device__ __forceinline__ unsigned long long fma2(unsigned long long a,
                                                   unsigned long long b,
                                                   unsigned long long c) {
    unsigned long long d;
    asm("fma.rn.f32x2 %0, %1, %2, %3;" : "=l"(d) : "l"(a), "l"(b), "l"(c));
    return d;
}

// load 16B from shared as two packed u64 (each = 2 floats)
__device__ __forceinline__ void lds_2x64(unsigned long long& a,
                                         unsigned long long& b, uint32_t addr) {
    asm volatile("ld.shared.v2.u64 {%0, %1}, [%2];"
                 : "=l"(a), "=l"(b) : "r"(addr));
}

__device__ __forceinline__ float hadd2(unsigned long long v) {
    float lo, hi;
    asm("mov.b64 {%0, %1}, %2;" : "=f"(lo), "=f"(hi) : "l"(v));
    return lo + hi;
}

__device__ __forceinline__ float tanh_ap(float x) {
    float y;
    asm("tanh.approx.f32 %0, %1;" : "=f"(y) : "f"(x));
    return y;
}

// gate activation: sigmoid via tanh identity (1 MUFU) or plain tanh
__device__ __forceinline__ float gate_act(float x, bool is_tanh) {
    float y = tanh_ap(is_tanh ? x : 0.5f * x);
    return is_tanh ? y : 0.5f * y + 0.5f;
}

// ================= Kernel A: embedding gather + x @ Wih0^T + (bih0+bhh0) =======
// smem: Wih0 as [256][132] fp32 (pad 128->132 : stride 528B, conflict-free LDS.128)
//       xs   as [8][128]   fp32 (8 tokens staged per tile)
#define KA_WPAD 132
#define KA_SMEM ((GDIM * KA_WPAD + 8 * EDIM) * 4)

__global__ void __launch_bounds__(256, 1)
embed_xproj_kernel(const int* __restrict__ seq,        // int32 tokens (JAX x64 off)
                   const float* __restrict__ emb,
                   const float* __restrict__ Wih0,
                   const float* __restrict__ bih0,
                   const float* __restrict__ bhh0) {
    extern __shared__ float sm[];
    float* Ws = sm;                  // 256*132
    float* xs = sm + GDIM * KA_WPAD; // 8*128
    const int tid = threadIdx.x;

    // stage weights [g][k] padded
    for (int i = tid; i < GDIM * (EDIM / 4); i += 256) {
        int g = i >> 5, k4 = i & 31;
        float4 w = ((const float4*)Wih0)[(size_t)g * (EDIM / 4) + k4];
        *(float4*)&Ws[g * KA_WPAD + k4 * 4] = w;
    }
    const float bsum = bih0[tid] + bhh0[tid];
    __syncthreads();

    const uint32_t s_w  = smem_u32(Ws) + tid * (KA_WPAD * 4);
    const uint32_t s_xs = smem_u32(xs);

    const int ntiles = BSZ * SLEN / 8;   // 32768
    for (int tile = blockIdx.x; tile < ntiles; tile += gridDim.x) {
        const int base = tile * 8;
        __syncthreads();   // previous tile's reads of xs are done
        {
            int tt = tid >> 5, k4 = tid & 31;
            int idx = seq[base + tt];
            idx = idx < 0 ? 0 : (idx >= EV ? EV - 1 : idx);   // defensive clamp
            float4 v = ((const float4*)emb)[(size_t)idx * (EDIM / 4) + k4];
            *(float4*)&xs[tt * EDIM + k4 * 4] = v;
        }
        __syncthreads();

        unsigned long long acc[8][2];
#pragma unroll
        for (int tt = 0; tt < 8; tt++) { acc[tt][0] = 0ULL; acc[tt][1] = 0ULL; }

#pragma unroll
        for (int k4 = 0; k4 < EDIM / 4; k4++) {
            unsigned long long w01, w23;
            lds_2x64(w01, w23, s_w + k4 * 16);
#pragma unroll
            for (int tt = 0; tt < 8; tt++) {
                unsigned long long x01, x23;
                lds_2x64(x01, x23, s_xs + (tt * EDIM + k4 * 4) * 4);
                acc[tt][0] = fma2(w01, x01, acc[tt][0]);
                acc[tt][1] = fma2(w23, x23, acc[tt][1]);
            }
        }
#pragma unroll
        for (int tt = 0; tt < 8; tt++) {
            float r = hadd2(acc[tt][0]) + hadd2(acc[tt][1]) + bsum;
            g_xproj[(size_t)(base + tt) * GDIM + tid] = r;
        }
    }
}

// ================= Kernel B: fused 2-layer recurrence + final FC ===============
// One CTA = 4 batch rows, all 512 timesteps. Weights resident in SMEM.
// W layout [g][k] padded 64->68 (stride 272B, conflict-free LDS.128).
#define KB_WPAD 68
#define KB_SMEM ((3 * GDIM * KB_WPAD + 2 * NB * HDIM + NB * GDIM) * 4)

__global__ void __launch_bounds__(256, 1)
lstm_rec_kernel(const float* __restrict__ Whh0,
                const float* __restrict__ Wih1,
                const float* __restrict__ Whh1,
                const float* __restrict__ bih1,
                const float* __restrict__ bhh1,
                const float* __restrict__ Wfc,
                const float* __restrict__ bfc,
                float* __restrict__ out) {
    extern __shared__ float sm[];
    float* W0s  = sm;                         // Whh0 [256][68]
    float* W1xs = W0s + GDIM * KB_WPAD;       // Wih1
    float* W1hs = W1xs + GDIM * KB_WPAD;      // Whh1
    float* h0s  = W1hs + GDIM * KB_WPAD;      // [4][64]
    float* h1s  = h0s + NB * HDIM;            // [4][64]
    float* gs   = h1s + NB * HDIM;            // [4][256] activated gates

    const int tid = threadIdx.x;

    for (int i = tid; i < GDIM * (HDIM / 4); i += 256) {
        int g = i >> 4, k4 = i & 15;
        *(float4*)&W0s [g * KB_WPAD + k4 * 4] = ((const float4*)Whh0)[i];
        *(float4*)&W1xs[g * KB_WPAD + k4 * 4] = ((const float4*)Wih1)[i];
        *(float4*)&W1hs[g * KB_WPAD + k4 * 4] = ((const float4*)Whh1)[i];
    }
    h0s[tid] = 0.0f;   // 256 floats each, 256 threads
    h1s[tid] = 0.0f;

    const float b1 = bih1[tid] + bhh1[tid];
    const bool my_tanh = (tid >= 128 && tid < 192);
    float c0[NB] = {0.f, 0.f, 0.f, 0.f};      // valid for tid < 64
    float c1[NB] = {0.f, 0.f, 0.f, 0.f};
    __syncthreads();

    const int b0 = blockIdx.x * NB;
    const float* xrow[NB];
#pragma unroll
    for (int nb = 0; nb < NB; nb++)
        xrow[nb] = g_xproj + (size_t)(b0 + nb) * SLEN * GDIM + tid;

    const uint32_t s_w0  = smem_u32(W0s)  + tid * (KB_WPAD * 4);
    const uint32_t s_w1x = smem_u32(W1xs) + tid * (KB_WPAD * 4);
    const uint32_t s_w1h = smem_u32(W1hs) + tid * (KB_WPAD * 4);
    const uint32_t s_h0  = smem_u32(h0s);
    const uint32_t s_h1  = smem_u32(h1s);

    float xcur[NB];
#pragma unroll
    for (int nb = 0; nb < NB; nb++) xcur[nb] = __ldg(xrow[nb]);

    for (int t = 0; t < SLEN; t++) {
        // prefetch next step's xproj rows (hidden under the matvecs)
        float xnxt[NB];
        const int tn = (t + 1 < SLEN) ? t + 1 : t;
#pragma unroll
        for (int nb = 0; nb < NB; nb++)
            xnxt[nb] = __ldg(xrow[nb] + (size_t)tn * GDIM);

        // ---- phase A: gates0 = xproj0[t] + Whh0 @ h0 ----
        unsigned long long aa[NB], ab[NB];
#pragma unroll
        for (int nb = 0; nb < NB; nb++) { aa[nb] = 0ULL; ab[nb] = 0ULL; }
#pragma unroll
        for (int k4 = 0; k4 < HDIM / 4; k4++) {
            unsigned long long w01, w23;
            lds_2x64(w01, w23, s_w0 + k4 * 16);
#pragma unroll
            for (int nb = 0; nb < NB; nb++) {
                unsigned long long h01, h23;
                lds_2x64(h01, h23, s_h0 + (nb * HDIM + k4 * 4) * 4);
                aa[nb] = fma2(w01, h01, aa[nb]);
                ab[nb] = fma2(w23, h23, ab[nb]);
            }
        }
#pragma unroll
        for (int nb = 0; nb < NB; nb++) {
            float v = hadd2(aa[nb]) + hadd2(ab[nb]) + xcur[nb];
            gs[nb * GDIM + tid] = gate_act(v, my_tanh);
        }
        __syncthreads();

        if (tid < HDIM) {
#pragma unroll
            for (int nb = 0; nb < NB; nb++) {
                const float* gb = gs + nb * GDIM;
                float gi = gb[tid], gf = gb[64 + tid];
                float gg = gb[128 + tid], go = gb[192 + tid];
                c0[nb] = gf * c0[nb] + gi * gg;
                h0s[nb * HDIM + tid] = go * tanh_ap(c0[nb]);
            }
        }
        __syncthreads();

        // ---- phase B: gates1 = Wih1 @ h0_new + Whh1 @ h1 + b1 ----
#pragma unroll
        for (int nb = 0; nb < NB; nb++) { aa[nb] = 0ULL; ab[nb] = 0ULL; }
#pragma unroll
        for (int k4 = 0; k4 < HDIM / 4; k4++) {
            unsigned long long wx01, wx23, wh01, wh23;
            lds_2x64(wx01, wx23, s_w1x + k4 * 16);
            lds_2x64(wh01, wh23, s_w1h + k4 * 16);
#pragma unroll
            for (int nb = 0; nb < NB; nb++) {
                unsigned long long p01, p23, q01, q23;
                lds_2x64(p01, p23, s_h0 + (nb * HDIM + k4 * 4) * 4);
                lds_2x64(q01, q23, s_h1 + (nb * HDIM + k4 * 4) * 4);
                aa[nb] = fma2(wx01, p01, aa[nb]);
                ab[nb] = fma2(wx23, p23, ab[nb]);
                aa[nb] = fma2(wh01, q01, aa[nb]);
                ab[nb] = fma2(wh23, q23, ab[nb]);
            }
        }
#pragma unroll
        for (int nb = 0; nb < NB; nb++) {
            float v = hadd2(aa[nb]) + hadd2(ab[nb]) + b1;
            gs[nb * GDIM + tid] = gate_act(v, my_tanh);
        }
        __syncthreads();

        if (tid < HDIM) {
#pragma unroll
            for (int nb = 0; nb < NB; nb++) {
                const float* gb = gs + nb * GDIM;
                float gi = gb[tid], gf = gb[64 + tid];
                float gg = gb[128 + tid], go = gb[192 + tid];
                c1[nb] = gf * c1[nb] + gi * gg;
                h1s[nb * HDIM + tid] = go * tanh_ap(c1[nb]);
            }
        }
        __syncthreads();

#pragma unroll
        for (int nb = 0; nb < NB; nb++) xcur[nb] = xnxt[nb];
    }

    // ---- epilogue: out = sigmoid(h1_final @ Wfc^T + bfc) ----
    if (tid < 2 * NB) {
        const int nb = tid >> 1, o = tid & 1;
        float s = bfc[o];
#pragma unroll
        for (int k = 0; k < HDIM; k++)
            s += Wfc[o * HDIM + k] * h1s[nb * HDIM + k];
        out[(b0 + nb) * 2 + o] = 1.0f / (1.0f + __expf(-s));
    }
}

// ================================ launcher =====================================
extern "C" void kernel_launch(void* const* d_in, const int* in_sizes, int n_in,
                              void* d_out, int out_size) {
    const int*   seq  = (const int*)d_in[0];
    const float* emb  = (const float*)d_in[1];
    const float* Wih0 = (const float*)d_in[2];
    const float* Whh0 = (const float*)d_in[3];
    const float* bih0 = (const float*)d_in[4];
    const float* bhh0 = (const float*)d_in[5];
    const float* Wih1 = (const float*)d_in[6];
    const float* Whh1 = (const float*)d_in[7];
    const float* bih1 = (const float*)d_in[8];
    const float* bhh1 = (const float*)d_in[9];
    const float* Wfc  = (const float*)d_in[10];
    const float* bfc  = (const float*)d_in[11];
    float* out = (float*)d_out;

    cudaFuncSetAttribute(embed_xproj_kernel,
                         cudaFuncAttributeMaxDynamicSharedMemorySize, KA_SMEM);
    cudaFuncSetAttribute(lstm_rec_kernel,
                         cudaFuncAttributeMaxDynamicSharedMemorySize, KB_SMEM);

    embed_xproj_kernel<<<152, 256, KA_SMEM>>>(seq, emb, Wih0, bih0, bhh0);
    lstm_rec_kernel<<<BSZ / NB, 256, KB_SMEM>>>(Whh0, Wih1, Whh1, bih1, bhh1,
                                                Wfc, bfc, out);
}

// round 4
// speedup vs baseline: 1.4175x; 1.4175x over previous
#include <cuda_runtime.h>
#include <cstdint>

#define EV 50000
#define EDIM 128
#define HDIM 64
#define GDIM 256
#define BSZ 512
#define SLEN 512
#define NB 4
typedef unsigned long long ull;

__device__ float g_xproj[(size_t)BSZ * SLEN * GDIM];

__device__ __forceinline__ uint32_t smem_u32(const void* p) {
    uint32_t a;
    asm("{ .reg .u64 t; cvta.to.shared.u64 t, %1; cvt.u32.u64 %0, t; }"
        : "=r"(a) : "l"(p));
    return a;
}
__device__ __forceinline__ ull fma2(ull a, ull b, ull c) {
    ull d; asm("fma.rn.f32x2 %0, %1, %2, %3;" : "=l"(d) : "l"(a), "l"(b), "l"(c));
    return d;
}
__device__ __forceinline__ void lds_2x64(ull& a, ull& b, uint32_t addr) {
    asm volatile("ld.shared.v2.u64 {%0, %1}, [%2];" : "=l"(a), "=l"(b) : "r"(addr));
}
__device__ __forceinline__ float hadd2(ull v) {
    float lo, hi; asm("mov.b64 {%0, %1}, %2;" : "=f"(lo), "=f"(hi) : "l"(v));
    return lo + hi;
}
__device__ __forceinline__ ull pack2(float lo, float hi) {
    ull d; asm("mov.b64 %0, {%1, %2};" : "=l"(d) : "f"(lo), "f"(hi));
    return d;
}
__device__ __forceinline__ float tanh_ap(float x) {
    float y; asm("tanh.approx.f32 %0, %1;" : "=f"(y) : "f"(x));
    return y;
}
__device__ __forceinline__ float gate_act(float x, bool is_tanh) {
    float y = tanh_ap(is_tanh ? x : 0.5f * x);
    return is_tanh ? y : 0.5f * y + 0.5f;
}

// ============ Kernel A: embed + x@Wih0^T + bias, 4 rows x 8 tokens / thread ====
#define KA_WPAD 132
#define KA_SMEM ((GDIM * KA_WPAD + 32 * KA_WPAD) * 4)

__global__ void __launch_bounds__(256, 1)
embed_xproj_kernel(const int* __restrict__ seq, const float* __restrict__ emb,
                   const float* __restrict__ Wih0, const float* __restrict__ bih0,
                   const float* __restrict__ bhh0) {
    extern __shared__ float sm[];
    float* Ws = sm;                   // [256][132]
    float* xs = sm + GDIM * KA_WPAD;  // [32][132]
    const int tid = threadIdx.x;
    const int j = tid & 63, tq = tid >> 6;

    for (int i = tid; i < GDIM * 32; i += 256) {
        int g = i >> 5, k4 = i & 31;
        *(float4*)&Ws[g * KA_WPAD + k4 * 4] =
            ((const float4*)Wih0)[(size_t)g * 32 + k4];
    }
    float bias[4];
#pragma unroll
    for (int q = 0; q < 4; q++) bias[q] = bih0[q * 64 + j] + bhh0[q * 64 + j];

    uint32_t s_w[4];
#pragma unroll
    for (int q = 0; q < 4; q++)
        s_w[q] = smem_u32(Ws) + (q * 64 + j) * (KA_WPAD * 4);
    const uint32_t s_xb = smem_u32(xs) + (tq * 8) * (KA_WPAD * 4);

    const int ntiles = (BSZ * SLEN) / 32;  // 8192
    const int mytok = tid >> 5, myk = tid & 31;
    float4 pf[4];

    auto ldx = [&](int tile) {
        const int base = tile * 32;
#pragma unroll
        for (int i = 0; i < 4; i++) {
            int idx = __ldg(seq + base + mytok + 8 * i);
            idx = idx < 0 ? 0 : (idx >= EV ? EV - 1 : idx);
            pf[i] = __ldg((const float4*)emb + (size_t)idx * 32 + myk);
        }
    };
    auto stx = [&]() {
#pragma unroll
        for (int i = 0; i < 4; i++)
            *(float4*)&xs[(mytok + 8 * i) * KA_WPAD + myk * 4] = pf[i];
    };

    int tile = blockIdx.x;
    if (tile < ntiles) ldx(tile);
    __syncthreads();
    if (tile < ntiles) stx();
    __syncthreads();

    for (; tile < ntiles; tile += gridDim.x) {
        const int nxt = tile + gridDim.x;
        if (nxt < ntiles) ldx(nxt);

        ull acc[4][8];
#pragma unroll
        for (int q = 0; q < 4; q++)
#pragma unroll
            for (int t = 0; t < 8; t++) acc[q][t] = 0ULL;

#pragma unroll 4
        for (int k4 = 0; k4 < 32; k4++) {
            ull w01[4], w23[4];
#pragma unroll
            for (int q = 0; q < 4; q++) lds_2x64(w01[q], w23[q], s_w[q] + k4 * 16);
#pragma unroll
            for (int t = 0; t < 8; t++) {
                ull x01, x23;
                lds_2x64(x01, x23, s_xb + t * (KA_WPAD * 4) + k4 * 16);
#pragma unroll
                for (int q = 0; q < 4; q++) {
                    acc[q][t] = fma2(w01[q], x01, acc[q][t]);
                    acc[q][t] = fma2(w23[q], x23, acc[q][t]);
                }
            }
        }
        const int gbase = tile * 32 + tq * 8;
#pragma unroll
        for (int t = 0; t < 8; t++) {
#pragma unroll
            for (int q = 0; q < 4; q++)
                g_xproj[(size_t)(gbase + t) * GDIM + q * 64 + j] =
                    hadd2(acc[q][t]) + bias[q];
        }
        __syncthreads();
        if (nxt < ntiles) stx();
        __syncthreads();
    }
}

// ============ Kernel B: recurrence; Wih1/Whh1 in registers =====================
#define KB_WPAD 68
#define KB_SMEM ((GDIM * KB_WPAD + 2 * NB * HDIM + NB * GDIM) * 4)

__global__ void __launch_bounds__(256, 1)
lstm_rec_kernel(const float* __restrict__ Whh0, const float* __restrict__ Wih1,
                const float* __restrict__ Whh1, const float* __restrict__ bih1,
                const float* __restrict__ bhh1, const float* __restrict__ Wfc,
                const float* __restrict__ bfc, float* __restrict__ out) {
    extern __shared__ float sm[];
    float* W0s = sm;                      // Whh0 [256][68]
    float* h0s = W0s + GDIM * KB_WPAD;    // [4][64]
    float* h1s = h0s + NB * HDIM;         // [4][64]
    float* gs  = h1s + NB * HDIM;         // [4][256]
    const int tid = threadIdx.x;

    for (int i = tid; i < GDIM * 16; i += 256) {
        int g = i >> 4, k4 = i & 15;
        *(float4*)&W0s[g * KB_WPAD + k4 * 4] = ((const float4*)Whh0)[i];
    }
    h0s[tid] = 0.0f;
    h1s[tid] = 0.0f;

    // phase-B weight rows in registers (row = tid), pre-paired over k
    ull w1x[32], w1h[32];
    {
        const float4* px = (const float4*)(Wih1 + tid * 64);
        const float4* ph = (const float4*)(Whh1 + tid * 64);
#pragma unroll
        for (int i = 0; i < 16; i++) {
            float4 vx = __ldg(px + i), vh = __ldg(ph + i);
            w1x[2 * i] = pack2(vx.x, vx.y); w1x[2 * i + 1] = pack2(vx.z, vx.w);
            w1h[2 * i] = pack2(vh.x, vh.y); w1h[2 * i + 1] = pack2(vh.z, vh.w);
        }
    }
    const float b1 = bih1[tid] + bhh1[tid];
    const bool my_tanh = (tid >= 128 && tid < 192);
    float c0[NB] = {0.f, 0.f, 0.f, 0.f};
    float c1[NB] = {0.f, 0.f, 0.f, 0.f};
    __syncthreads();

    const int b0 = blockIdx.x * NB;
    const float* xrow[NB];
#pragma unroll
    for (int nb = 0; nb < NB; nb++)
        xrow[nb] = g_xproj + (size_t)(b0 + nb) * SLEN * GDIM + tid;

    const uint32_t s_w0 = smem_u32(W0s) + tid * (KB_WPAD * 4);
    const uint32_t s_h0 = smem_u32(h0s);
    const uint32_t s_h1 = smem_u32(h1s);

    float xcur[NB];
#pragma unroll
    for (int nb = 0; nb < NB; nb++) xcur[nb] = __ldg(xrow[nb]);

    for (int t = 0; t < SLEN; t++) {
        float xnxt[NB];
        const int tn = (t + 1 < SLEN) ? t + 1 : t;
#pragma unroll
        for (int nb = 0; nb < NB; nb++)
            xnxt[nb] = __ldg(xrow[nb] + (size_t)tn * GDIM);

        // phase A: gates0 = xproj[t] + Whh0 @ h0
        ull aa[NB], ab[NB];
#pragma unroll
        for (int nb = 0; nb < NB; nb++) { aa[nb] = 0; ab[nb] = 0; }
#pragma unroll
        for (int k4 = 0; k4 < 16; k4++) {
            ull w01, w23;
            lds_2x64(w01, w23, s_w0 + k4 * 16);
#pragma unroll
            for (int nb = 0; nb < NB; nb++) {
                ull h01, h23;
                lds_2x64(h01, h23, s_h0 + (nb * HDIM + k4 * 4) * 4);
                aa[nb] = fma2(w01, h01, aa[nb]);
                ab[nb] = fma2(w23, h23, ab[nb]);
            }
        }
#pragma unroll
        for (int nb = 0; nb < NB; nb++)
            gs[nb * GDIM + tid] =
                gate_act(hadd2(aa[nb]) + hadd2(ab[nb]) + xcur[nb], my_tanh);
        __syncthreads();

        if (tid < HDIM) {
#pragma unroll
            for (int nb = 0; nb < NB; nb++) {
                const float* gb = gs + nb * GDIM;
                float gi = gb[tid], gf = gb[64 + tid];
                float gg = gb[128 + tid], go = gb[192 + tid];
                c0[nb] = gf * c0[nb] + gi * gg;
                h0s[nb * HDIM + tid] = go * tanh_ap(c0[nb]);
            }
        }
        __syncthreads();

        // phase B: gates1 = Wih1(reg) @ h0new + Whh1(reg) @ h1 + b1
#pragma unroll
        for (int nb = 0; nb < NB; nb++) { aa[nb] = 0; ab[nb] = 0; }
#pragma unroll
        for (int k4 = 0; k4 < 16; k4++) {
#pragma unroll
            for (int nb = 0; nb < NB; nb++) {
                ull p01, p23, q01, q23;
                lds_2x64(p01, p23, s_h0 + (nb * HDIM + k4 * 4) * 4);
                lds_2x64(q01, q23, s_h1 + (nb * HDIM + k4 * 4) * 4);
                aa[nb] = fma2(w1x[2 * k4], p01, aa[nb]);
                ab[nb] = fma2(w1x[2 * k4 + 1], p23, ab[nb]);
                aa[nb] = fma2(w1h[2 * k4], q01, aa[nb]);
                ab[nb] = fma2(w1h[2 * k4 + 1], q23, ab[nb]);
            }
        }
#pragma unroll
        for (int nb = 0; nb < NB; nb++)
            gs[nb * GDIM + tid] =
                gate_act(hadd2(aa[nb]) + hadd2(ab[nb]) + b1, my_tanh);
        __syncthreads();

        if (tid < HDIM) {
#pragma unroll
            for (int nb = 0; nb < NB; nb++) {
                const float* gb = gs + nb * GDIM;
                float gi = gb[tid], gf = gb[64 + tid];
                float gg = gb[128 + tid], go = gb[192 + tid];
                c1[nb] = gf * c1[nb] + gi * gg;
                h1s[nb * HDIM + tid] = go * tanh_ap(c1[nb]);
            }
        }
        __syncthreads();

#pragma unroll
        for (int nb = 0; nb < NB; nb++) xcur[nb] = xnxt[nb];
    }

    if (tid < 2 * NB) {
        const int nb = tid >> 1, o = tid & 1;
        float s = bfc[o];
#pragma unroll
        for (int k = 0; k < HDIM; k++)
            s += Wfc[o * HDIM + k] * h1s[nb * HDIM + k];
        out[(b0 + nb) * 2 + o] = 1.0f / (1.0f + __expf(-s));
    }
}

// ================================ launcher =====================================
extern "C" void kernel_launch(void* const* d_in, const int* in_sizes, int n_in,
                              void* d_out, int out_size) {
    const int*   seq  = (const int*)d_in[0];
    const float* emb  = (const float*)d_in[1];
    const float* Wih0 = (const float*)d_in[2];
    const float* Whh0 = (const float*)d_in[3];
    const float* bih0 = (const float*)d_in[4];
    const float* bhh0 = (const float*)d_in[5];
    const float* Wih1 = (const float*)d_in[6];
    const float* Whh1 = (const float*)d_in[7];
    const float* bih1 = (const float*)d_in[8];
    const float* bhh1 = (const float*)d_in[9];
    const float* Wfc  = (const float*)d_in[10];
    const float* bfc  = (const float*)d_in[11];
    float* out = (float*)d_out;

    cudaFuncSetAttribute(embed_xproj_kernel,
                         cudaFuncAttributeMaxDynamicSharedMemorySize, KA_SMEM);
    cudaFuncSetAttribute(lstm_rec_kernel,
                         cudaFuncAttributeMaxDynamicSharedMemorySize, KB_SMEM);

    embed_xproj_kernel<<<152, 256, KA_SMEM>>>(seq, emb, Wih0, bih0, bhh0);
    lstm_rec_kernel<<<BSZ / NB, 256, KB_SMEM>>>(Whh0, Wih1, Whh1, bih1, bhh1,
                                                Wfc, bfc, out);
}